// round 3
// baseline (speedup 1.0000x reference)
#include <cuda_runtime.h>
#include <cstdint>

// Problem constants
#define IN_F   4096
#define OUT_F  4096
#define NGROUPS (OUT_F * IN_F / 32)

// 64 MB fp32 dequantized weight scratch (device global: allocation-guard safe)
__device__ float g_W[(size_t)OUT_F * IN_F];

// ---------------------------------------------------------------------------
// Kernel 1: 3-bit group dequant.
// The harness widens int8 inputs to int32: one int32 element per packed BYTE.
// Each group = 12 int32 elements (12 bytes of packed data) -> 32 floats.
// Bit layout within each 3-byte chunk = little-endian 24-bit, 3-bit fields.
// w = (q/7)*(2n) - n = q*(2n/7) - n
// ---------------------------------------------------------------------------
__global__ void dequant3_kernel(const int* __restrict__ packed_i32,
                                const float* __restrict__ norm) {
    int g = blockIdx.x * blockDim.x + threadIdx.x;
    if (g >= NGROUPS) return;

    // Load 12 int32 "bytes" for this group (three int4 vector loads).
    const int4* p = reinterpret_cast<const int4*>(packed_i32 + (size_t)g * 12);
    int4 q0 = p[0], q1 = p[1], q2 = p[2];
    uint32_t b[12];
    b[0]  = (uint32_t)q0.x & 0xFF; b[1]  = (uint32_t)q0.y & 0xFF;
    b[2]  = (uint32_t)q0.z & 0xFF; b[3]  = (uint32_t)q0.w & 0xFF;
    b[4]  = (uint32_t)q1.x & 0xFF; b[5]  = (uint32_t)q1.y & 0xFF;
    b[6]  = (uint32_t)q1.z & 0xFF; b[7]  = (uint32_t)q1.w & 0xFF;
    b[8]  = (uint32_t)q2.x & 0xFF; b[9]  = (uint32_t)q2.y & 0xFF;
    b[10] = (uint32_t)q2.z & 0xFF; b[11] = (uint32_t)q2.w & 0xFF;

    float n = norm[g];
    float s = n * (2.0f / 7.0f);

    float* out = g_W + (size_t)g * 32;
#pragma unroll
    for (int c = 0; c < 4; ++c) {
        uint32_t u = b[3 * c] | (b[3 * c + 1] << 8) | (b[3 * c + 2] << 16);
        float4 lo, hi;
        lo.x = (float)( u        & 7) * s - n;
        lo.y = (float)((u >> 3)  & 7) * s - n;
        lo.z = (float)((u >> 6)  & 7) * s - n;
        lo.w = (float)((u >> 9)  & 7) * s - n;
        hi.x = (float)((u >> 12) & 7) * s - n;
        hi.y = (float)((u >> 15) & 7) * s - n;
        hi.z = (float)((u >> 18) & 7) * s - n;
        hi.w = (float)((u >> 21) & 7) * s - n;
        *reinterpret_cast<float4*>(out + c * 8)     = lo;
        *reinterpret_cast<float4*>(out + c * 8 + 4) = hi;
    }
}

// ---------------------------------------------------------------------------
// Kernel 2: fp32 GEMM  C[M,N] = A[M,K] * B[N,K]^T + bias.
// Plain fp32 FFMA accumulators, BM=BN=128, BK=8, 256 threads,
// 8x8 per-thread microtile, register-prefetched k-tiles.
// ---------------------------------------------------------------------------
#define BM 128
#define BN 128
#define BK 8

__global__ __launch_bounds__(256, 2)
void gemm_nt_bias(const float* __restrict__ A,     // [M, K]
                  const float* __restrict__ bias,  // [N]
                  float* __restrict__ C,           // [M, N]
                  int M) {
    __shared__ __align__(16) float As[BK][BM];
    __shared__ __align__(16) float Bs[BK][BN];

    const float* B = g_W;   // [N, K]

    const int tid = threadIdx.x;
    const int bm = blockIdx.y * BM;
    const int bn = blockIdx.x * BN;

    // global->smem loader mapping: each thread loads one float4 of A and B
    const int lrow = tid >> 1;        // 0..127 (row within tile)
    const int lk   = (tid & 1) * 4;   // k offset 0 or 4

    const float* Ag = A + (size_t)(bm + lrow) * IN_F + lk;
    const float* Bg = B + (size_t)(bn + lrow) * IN_F + lk;

    float4 aReg = *reinterpret_cast<const float4*>(Ag);
    float4 bReg = *reinterpret_cast<const float4*>(Bg);

    const int ty = tid >> 4;   // 0..15  -> rows  ty*8..ty*8+7
    const int tx = tid & 15;   // 0..15  -> cols  tx*8..tx*8+7

    float acc[8][8];
#pragma unroll
    for (int i = 0; i < 8; ++i)
#pragma unroll
        for (int j = 0; j < 8; ++j) acc[i][j] = 0.0f;

    const int KT = IN_F / BK;
    for (int kt = 0; kt < KT; ++kt) {
        As[lk + 0][lrow] = aReg.x; As[lk + 1][lrow] = aReg.y;
        As[lk + 2][lrow] = aReg.z; As[lk + 3][lrow] = aReg.w;
        Bs[lk + 0][lrow] = bReg.x; Bs[lk + 1][lrow] = bReg.y;
        Bs[lk + 2][lrow] = bReg.z; Bs[lk + 3][lrow] = bReg.w;
        __syncthreads();

        if (kt + 1 < KT) {  // prefetch next k-tile
            aReg = *reinterpret_cast<const float4*>(Ag + (size_t)(kt + 1) * BK);
            bReg = *reinterpret_cast<const float4*>(Bg + (size_t)(kt + 1) * BK);
        }

#pragma unroll
        for (int k = 0; k < BK; ++k) {
            float4 a0 = *reinterpret_cast<const float4*>(&As[k][ty * 8]);
            float4 a1 = *reinterpret_cast<const float4*>(&As[k][ty * 8 + 4]);
            float4 b0 = *reinterpret_cast<const float4*>(&Bs[k][tx * 8]);
            float4 b1 = *reinterpret_cast<const float4*>(&Bs[k][tx * 8 + 4]);

            float a[8] = {a0.x, a0.y, a0.z, a0.w, a1.x, a1.y, a1.z, a1.w};
            float b[8] = {b0.x, b0.y, b0.z, b0.w, b1.x, b1.y, b1.z, b1.w};

#pragma unroll
            for (int i = 0; i < 8; ++i)
#pragma unroll
                for (int j = 0; j < 8; ++j)
                    acc[i][j] = fmaf(a[i], b[j], acc[i][j]);
        }
        __syncthreads();
    }

    // epilogue: acc + bias -> C (vectorized float4 stores)
#pragma unroll
    for (int i = 0; i < 8; ++i) {
        int row = bm + ty * 8 + i;
        float* Cp = C + (size_t)row * OUT_F + bn + tx * 8;
        float4 v0, v1;
        v0.x = acc[i][0] + bias[bn + tx * 8 + 0];
        v0.y = acc[i][1] + bias[bn + tx * 8 + 1];
        v0.z = acc[i][2] + bias[bn + tx * 8 + 2];
        v0.w = acc[i][3] + bias[bn + tx * 8 + 3];
        v1.x = acc[i][4] + bias[bn + tx * 8 + 4];
        v1.y = acc[i][5] + bias[bn + tx * 8 + 5];
        v1.z = acc[i][6] + bias[bn + tx * 8 + 6];
        v1.w = acc[i][7] + bias[bn + tx * 8 + 7];
        *reinterpret_cast<float4*>(Cp)     = v0;
        *reinterpret_cast<float4*>(Cp + 4) = v1;
    }
}

// ---------------------------------------------------------------------------
// Launch: inputs in metadata order: x (f32), weight_q3 (int8->int32 widened),
// weight_norm (f32), bias (f32).  Output f32 [2,2048,4096].
// ---------------------------------------------------------------------------
extern "C" void kernel_launch(void* const* d_in, const int* in_sizes, int n_in,
                              void* d_out, int out_size) {
    const float* x    = (const float*)d_in[0];
    const int*   wq   = (const int*)d_in[1];     // int8 widened to int32 by harness
    const float* wn   = (const float*)d_in[2];
    const float* bias = (const float*)d_in[3];
    float* out = (float*)d_out;

    const int M = in_sizes[0] / IN_F;   // 4096

    dequant3_kernel<<<NGROUPS / 256, 256>>>(wq, wn);

    dim3 grid(OUT_F / BN, M / BM);
    gemm_nt_bias<<<grid, 256>>>(x, bias, out, M);
}

// round 14
// speedup vs baseline: 5.6324x; 5.6324x over previous
#include <cuda_runtime.h>
#include <cuda_fp16.h>
#include <mma.h>
#include <cstdint>

using namespace nvcuda;

// ---------------------------------------------------------------------------
// Problem constants
// ---------------------------------------------------------------------------
#define IN_F    4096
#define OUT_F   4096
#define M_TOTAL 4096
#define NGROUPS (OUT_F * IN_F / 32)

// Staging buffers (device globals: allocation-guard safe).
__device__ __half g_X16[(size_t)M_TOTAL * IN_F];   // 32 MB
__device__ __half g_W16[(size_t)OUT_F * IN_F];     // 32 MB
__device__ float  g_biasT[16 * OUT_F];             // bias replicated over 16 rows

// ---------------------------------------------------------------------------
// helpers
// ---------------------------------------------------------------------------
__device__ __forceinline__ uint32_t smem_u32(const void* p) {
    uint32_t a;
    asm("{ .reg .u64 t; cvta.to.shared.u64 t, %1; cvt.u32.u64 %0, t; }"
        : "=r"(a) : "l"(p));
    return a;
}
__device__ __forceinline__ void cp16(uint32_t dst, const void* src) {
    asm volatile("cp.async.cg.shared.global [%0], [%1], 16;"
                 :: "r"(dst), "l"(src) : "memory");
}
#define CP_COMMIT() asm volatile("cp.async.commit_group;" ::: "memory")
#define CP_WAIT(n)  asm volatile("cp.async.wait_group %0;" :: "n"(n) : "memory")

// ---------------------------------------------------------------------------
// Kernel 1: 3-bit dequant -> fp16 weights (harness widens int8 to int32:
// one int32 element per packed byte; 12 "bytes" per 32-value group)
// w = q * (2n/7) - n
// ---------------------------------------------------------------------------
__global__ void dequant3_f16(const int* __restrict__ packed_i32,
                             const float* __restrict__ norm) {
    int g = blockIdx.x * blockDim.x + threadIdx.x;
    if (g >= NGROUPS) return;

    const int4* p = reinterpret_cast<const int4*>(packed_i32 + (size_t)g * 12);
    int4 q0 = p[0], q1 = p[1], q2 = p[2];
    uint32_t b[12];
    b[0]  = (uint32_t)q0.x & 0xFF; b[1]  = (uint32_t)q0.y & 0xFF;
    b[2]  = (uint32_t)q0.z & 0xFF; b[3]  = (uint32_t)q0.w & 0xFF;
    b[4]  = (uint32_t)q1.x & 0xFF; b[5]  = (uint32_t)q1.y & 0xFF;
    b[6]  = (uint32_t)q1.z & 0xFF; b[7]  = (uint32_t)q1.w & 0xFF;
    b[8]  = (uint32_t)q2.x & 0xFF; b[9]  = (uint32_t)q2.y & 0xFF;
    b[10] = (uint32_t)q2.z & 0xFF; b[11] = (uint32_t)q2.w & 0xFF;

    float n = norm[g];
    float s = n * (2.0f / 7.0f);

    __half* out = g_W16 + (size_t)g * 32;
#pragma unroll
    for (int c = 0; c < 4; ++c) {
        uint32_t u = b[3 * c] | (b[3 * c + 1] << 8) | (b[3 * c + 2] << 16);
        float v[8];
#pragma unroll
        for (int i = 0; i < 8; ++i)
            v[i] = (float)((u >> (3 * i)) & 7) * s - n;
        __half2 h0 = __floats2half2_rn(v[0], v[1]);
        __half2 h1 = __floats2half2_rn(v[2], v[3]);
        __half2 h2 = __floats2half2_rn(v[4], v[5]);
        __half2 h3 = __floats2half2_rn(v[6], v[7]);
        uint4 pk;
        pk.x = *reinterpret_cast<uint32_t*>(&h0);
        pk.y = *reinterpret_cast<uint32_t*>(&h1);
        pk.z = *reinterpret_cast<uint32_t*>(&h2);
        pk.w = *reinterpret_cast<uint32_t*>(&h3);
        *reinterpret_cast<uint4*>(out + c * 8) = pk;
    }
}

// ---------------------------------------------------------------------------
// Kernel 2: fp32 -> fp16 activation convert (8 elements / thread)
// ---------------------------------------------------------------------------
__global__ void cvt_x_f16(const float* __restrict__ x) {
    size_t i = ((size_t)blockIdx.x * blockDim.x + threadIdx.x) * 8;
    float4 f0 = *reinterpret_cast<const float4*>(x + i);
    float4 f1 = *reinterpret_cast<const float4*>(x + i + 4);
    __half2 h0 = __floats2half2_rn(f0.x, f0.y);
    __half2 h1 = __floats2half2_rn(f0.z, f0.w);
    __half2 h2 = __floats2half2_rn(f1.x, f1.y);
    __half2 h3 = __floats2half2_rn(f1.z, f1.w);
    uint4 pk;
    pk.x = *reinterpret_cast<uint32_t*>(&h0);
    pk.y = *reinterpret_cast<uint32_t*>(&h1);
    pk.z = *reinterpret_cast<uint32_t*>(&h2);
    pk.w = *reinterpret_cast<uint32_t*>(&h3);
    *reinterpret_cast<uint4*>(g_X16 + i) = pk;
}

// ---------------------------------------------------------------------------
// Kernel 3: replicate bias into a 16-row tile (accumulator-init source)
// ---------------------------------------------------------------------------
__global__ void fill_biasT(const float* __restrict__ bias) {
    int i = blockIdx.x * blockDim.x + threadIdx.x;   // 0 .. 16*4096-1
    g_biasT[i] = bias[i & (OUT_F - 1)];
}

// ---------------------------------------------------------------------------
// Kernel 4: WMMA fp16 GEMM, fp32 accum.  C[M,N] = X[M,K] * W[N,K]^T + bias.
// BM=BN=128, BK=32, 256 threads (8 warps: 2 along M x 4 along N),
// warp tile 64x32 = 4x2 wmma 16x16x16 fragments.
// 2-stage cp.async double buffer; smem rows padded +8 halves (16B) for
// conflict-free, 16B-aligned fragment rows.
// ---------------------------------------------------------------------------
#define BM 128
#define BN 128
#define BK 32
#define KT_CNT (IN_F / BK)    // 128
#define SKEW 8                // halves

__global__ __launch_bounds__(256, 2)
void gemm_wmma(float* __restrict__ C) {
    __shared__ __half As[2][BM][BK + SKEW];   // 2*128*40*2B = 20480 B
    __shared__ __half Bs[2][BN][BK + SKEW];   // 20480 B

    const int tid = threadIdx.x;
    const int wid = tid >> 5;
    const int bm = blockIdx.y * BM;
    const int bn = blockIdx.x * BN;
    const int wm = (wid & 1) * 64;    // warp M offset in tile
    const int wn = (wid >> 1) * 32;   // warp N offset in tile

    // loader mapping: thread t -> row t/2, 32B chunk (t&1)
    const int lrow = tid >> 1;
    const int lh0  = (tid & 1) * 16;  // half offset within row

    wmma::fragment<wmma::accumulator, 16, 16, 16, float> acc[4][2];
#pragma unroll
    for (int i = 0; i < 4; ++i)
#pragma unroll
        for (int j = 0; j < 2; ++j)
            wmma::load_matrix_sync(acc[i][j],
                                   g_biasT + bn + wn + j * 16,
                                   OUT_F, wmma::mem_row_major);

    // prologue: k-tile 0 into stage 0
    {
        const __half* Ag = g_X16 + (size_t)(bm + lrow) * IN_F + lh0;
        cp16(smem_u32(&As[0][lrow][lh0]),     Ag);
        cp16(smem_u32(&As[0][lrow][lh0 + 8]), Ag + 8);
        const __half* Bg = g_W16 + (size_t)(bn + lrow) * IN_F + lh0;
        cp16(smem_u32(&Bs[0][lrow][lh0]),     Bg);
        cp16(smem_u32(&Bs[0][lrow][lh0 + 8]), Bg + 8);
        CP_COMMIT();
    }

    for (int kt = 0; kt < KT_CNT; ++kt) {
        const int s = kt & 1;
        if (kt + 1 < KT_CNT) {
            const int ns = s ^ 1;
            const int kof = (kt + 1) * BK;
            const __half* Ag = g_X16 + (size_t)(bm + lrow) * IN_F + kof + lh0;
            cp16(smem_u32(&As[ns][lrow][lh0]),     Ag);
            cp16(smem_u32(&As[ns][lrow][lh0 + 8]), Ag + 8);
            const __half* Bg = g_W16 + (size_t)(bn + lrow) * IN_F + kof + lh0;
            cp16(smem_u32(&Bs[ns][lrow][lh0]),     Bg);
            cp16(smem_u32(&Bs[ns][lrow][lh0 + 8]), Bg + 8);
            CP_COMMIT();
            CP_WAIT(1);        // k-tile kt resident
        } else {
            CP_WAIT(0);
        }
        __syncthreads();

#pragma unroll
        for (int ks = 0; ks < 2; ++ks) {
            wmma::fragment<wmma::matrix_a, 16, 16, 16, __half, wmma::row_major> a[4];
            wmma::fragment<wmma::matrix_b, 16, 16, 16, __half, wmma::col_major> b[2];
#pragma unroll
            for (int i = 0; i < 4; ++i)
                wmma::load_matrix_sync(a[i], &As[s][wm + i * 16][ks * 16], BK + SKEW);
#pragma unroll
            for (int j = 0; j < 2; ++j)
                wmma::load_matrix_sync(b[j], &Bs[s][wn + j * 16][ks * 16], BK + SKEW);
#pragma unroll
            for (int i = 0; i < 4; ++i)
#pragma unroll
                for (int j = 0; j < 2; ++j)
                    wmma::mma_sync(acc[i][j], a[i], b[j], acc[i][j]);
        }
        __syncthreads();   // protect stage s from being overwritten next iter
    }

    // epilogue: store accumulators (bias already folded in)
#pragma unroll
    for (int i = 0; i < 4; ++i)
#pragma unroll
        for (int j = 0; j < 2; ++j)
            wmma::store_matrix_sync(
                C + (size_t)(bm + wm + i * 16) * OUT_F + bn + wn + j * 16,
                acc[i][j], OUT_F, wmma::mem_row_major);
}

// ---------------------------------------------------------------------------
// Launch.  Inputs: x (f32), weight_q3 (int8->int32 widened), weight_norm (f32),
// bias (f32).  Output f32 [2,2048,4096].
// ---------------------------------------------------------------------------
extern "C" void kernel_launch(void* const* d_in, const int* in_sizes, int n_in,
                              void* d_out, int out_size) {
    const float* x    = (const float*)d_in[0];
    const int*   wq   = (const int*)d_in[1];
    const float* wn   = (const float*)d_in[2];
    const float* bias = (const float*)d_in[3];
    float* out = (float*)d_out;

    const size_t n_x = (size_t)M_TOTAL * IN_F;

    dequant3_f16<<<NGROUPS / 256, 256>>>(wq, wn);
    cvt_x_f16<<<(int)(n_x / 8 / 256), 256>>>(x);
    fill_biasT<<<16 * OUT_F / 256, 256>>>(bias);

    dim3 grid(OUT_F / BN, M_TOTAL / BM);
    gemm_wmma<<<grid, 256>>>(out);
}